// round 6
// baseline (speedup 1.0000x reference)
#include <cuda_runtime.h>
#include <math.h>

// Problem shapes (fixed by the reference)
#define BATCH      16384
#define N_FEATURES 128
#define HIDDEN     64
#define NUM_TASKS  50000

// Bucketing: task >> 7 -> 391 bins. Bin granularity doesn't matter for dedup:
// duplicates of a task share a bin -> land within ~42 adjacent perm slots ->
// processed concurrently by the 8288 resident warps -> L2 dedup of 32KB tiles.
#define BIN_SHIFT 7
#define NBINS     391            // ceil(50000 / 128)

#define THREADS   64             // 2 warps per CTA
#define CTAS      4144           // 148 * 28 -> all-resident (launch_bounds(64,28))
#define NWARPS    (CTAS * 2)     // 8288

__device__ int g_hist[NBINS];       // zero at load; re-zeroed in phase C each run
__device__ int g_cursor[NBINS];     // recomputed each run
__device__ int g_perm[BATCH];       // packed: (task << 14) | sample
__device__ unsigned g_cnt_leaf[64]; // self-resetting barrier counters
__device__ unsigned g_cnt_root;
__device__ volatile unsigned g_rel[3];  // rotating release flags (replay-invariant cycle)

// Two-level grid barrier. Safe: all CTAS co-resident (148*28, regs pinned by
// __launch_bounds__(64,28)). Counters self-reset; flag cycle returns to the
// same state every replay, so graph replays behave identically.
__device__ __forceinline__ void grid_barrier(int cta, int k) {
    __syncthreads();
    if (threadIdx.x == 0) {
        __threadfence();
        const int leaf = cta & 63;                        // 4144 = 48*65 + 16*64
        const unsigned leafN = 64u + (leaf < 48 ? 1u : 0u);
        if (atomicAdd(&g_cnt_leaf[leaf], 1u) == leafN - 1u) {
            atomicExch(&g_cnt_leaf[leaf], 0u);
            if (atomicAdd(&g_cnt_root, 1u) == 63u) {
                atomicExch(&g_cnt_root, 0u);
                g_rel[(k + 2) % 3] = 0u;                  // clear previous flag
                __threadfence();
                g_rel[k] = 1u;                            // release
            }
        }
        while (g_rel[k] == 0u) __nanosleep(64);
        __threadfence();
    }
    __syncthreads();
}

// exact GELU: 0.5*x*(1+erf(x/sqrt(2)))
__device__ __forceinline__ float gelu_exact(float v) {
    return 0.5f * v * (1.0f + erff(v * 0.70710678118654752f));
}

struct EpiIn { float a0, a1, a2, a3; };

__device__ __forceinline__ void epilogue_store(
    int task, int sample, int lane, int tc, EpiIn e,
    const float* __restrict__ l1_bias, const float* __restrict__ l2_emb,
    const float* __restrict__ l2_bias, float* __restrict__ out)
{
    // fold 2-way F split
    e.a0 += __shfl_xor_sync(0xffffffffu, e.a0, 16);
    e.a1 += __shfl_xor_sync(0xffffffffu, e.a1, 16);
    e.a2 += __shfl_xor_sync(0xffffffffu, e.a2, 16);
    e.a3 += __shfl_xor_sync(0xffffffffu, e.a3, 16);

    const float4 b1 = reinterpret_cast<const float4*>(l1_bias + (size_t)task * HIDDEN)[tc];
    const float4 w2 = reinterpret_cast<const float4*>(l2_emb  + (size_t)task * HIDDEN)[tc];

    float h0 = gelu_exact(e.a0 + b1.x);
    float h1 = gelu_exact(e.a1 + b1.y);
    float h2 = gelu_exact(e.a2 + b1.z);
    float h3 = gelu_exact(e.a3 + b1.w);

    float dot = fmaf(h0, w2.x, fmaf(h1, w2.y, fmaf(h2, w2.z, h3 * w2.w)));
    dot += __shfl_xor_sync(0xffffffffu, dot, 8);
    dot += __shfl_xor_sync(0xffffffffu, dot, 4);
    dot += __shfl_xor_sync(0xffffffffu, dot, 2);
    dot += __shfl_xor_sync(0xffffffffu, dot, 1);

    if (lane == 0) out[sample] = dot + __ldg(l2_bias + task);
}

__global__ __launch_bounds__(THREADS, 28)
void hypernet_fused(const float* __restrict__ x,
                    const int*   __restrict__ task_ids,
                    const float* __restrict__ l1_emb,   // [NUM_TASKS, 128*64]
                    const float* __restrict__ l1_bias,  // [NUM_TASKS, 64]
                    const float* __restrict__ l2_emb,   // [NUM_TASKS, 64]
                    const float* __restrict__ l2_bias,  // [NUM_TASKS, 1]
                    float*       __restrict__ out)      // [BATCH, 1]
{
    __shared__ float xs[2][2][N_FEATURES];   // [warp][slot-phase][feature]
    __shared__ int   warp_sums[2];

    const int cta  = blockIdx.x;
    const int tid  = threadIdx.x;
    const int warp = tid >> 5;
    const int lane = tid & 31;

    // ---------- Phase A: histogram (4 samples per CTA) ----------
    if (tid < 4) {
        int s = cta * 4 + tid;
        if (s < BATCH) atomicAdd(&g_hist[task_ids[s] >> BIN_SHIFT], 1);
    }
    grid_barrier(cta, 0);

    // ---------- Phase B: exclusive scan of 391 bins (CTA 0, ~1us) ----------
    if (cta == 0) {
        const int BPT = 7;                       // 64*7 = 448 >= 391
        const int lo = tid * BPT;
        const int hi = min(lo + BPT, NBINS);
        int s = 0;
        #pragma unroll
        for (int b = lo; b < hi; ++b) s += g_hist[b];
        int v = s;
        #pragma unroll
        for (int off = 1; off < 32; off <<= 1) {
            int u = __shfl_up_sync(0xffffffffu, v, off);
            if (lane >= off) v += u;
        }
        if (lane == 31) warp_sums[warp] = v;
        __syncthreads();
        int run = v - s + (warp == 1 ? warp_sums[0] : 0);  // exclusive prefix
        for (int b = lo; b < hi; ++b) {
            int c = g_hist[b];
            g_cursor[b] = run;
            run += c;
        }
    }
    grid_barrier(cta, 1);

    // ---------- Phase C: scatter (packed task|sample) + hist reset ----------
    if (tid < 4) {
        int s = cta * 4 + tid;
        if (s < BATCH) {
            int t = task_ids[s];
            int pos = atomicAdd(&g_cursor[t >> BIN_SHIFT], 1);
            g_perm[pos] = (t << 14) | s;
        }
    }
    if (tid == 0 && cta < NBINS) g_hist[cta] = 0;
    grid_barrier(cta, 2);

    // ---------- Phase D: pipelined main compute, 2 slots per warp ----------
    const int wgid = cta * 2 + warp;
    const int tf = lane >> 4;
    const int tc = lane & 15;

    // slot 0: load + stage
    const int v0 = g_perm[wgid];
    const int s0 = v0 & 0x3FFF;
    const int t0 = v0 >> 14;
    reinterpret_cast<float4*>(xs[warp][0])[lane] =
        reinterpret_cast<const float4*>(x + (size_t)s0 * N_FEATURES)[lane];

    // prefetch slot 1 NOW: its perm load + x stage fly during slot-0's W1 loop
    const int  slot1 = wgid + NWARPS;
    const bool has2  = slot1 < BATCH;
    int s1 = 0, t1 = 0;
    if (has2) {
        const int v1 = g_perm[slot1];
        s1 = v1 & 0x3FFF;
        t1 = v1 >> 14;
        reinterpret_cast<float4*>(xs[warp][1])[lane] =
            reinterpret_cast<const float4*>(x + (size_t)s1 * N_FEATURES)[lane];
    }
    __syncwarp();

    // slot 0: W1 loop (64 coalesced 512B sweeps per warp)
    {
        const float4* w1v = reinterpret_cast<const float4*>(
            l1_emb + (size_t)t0 * (N_FEATURES * HIDDEN)) + tf * 16 + tc;
        EpiIn e = {0.f, 0.f, 0.f, 0.f};
        #pragma unroll 16
        for (int i = 0; i < N_FEATURES / 2; ++i) {
            const int f = tf + 2 * i;
            float  xv = xs[warp][0][f];
            float4 wv = w1v[i * 32];
            e.a0 = fmaf(xv, wv.x, e.a0);
            e.a1 = fmaf(xv, wv.y, e.a1);
            e.a2 = fmaf(xv, wv.z, e.a2);
            e.a3 = fmaf(xv, wv.w, e.a3);
        }
        epilogue_store(t0, s0, lane, tc, e, l1_bias, l2_emb, l2_bias, out);
    }

    // slot 1: x already staged, task known -> W1 loads issue immediately
    if (has2) {
        __syncwarp();
        const float4* w1v = reinterpret_cast<const float4*>(
            l1_emb + (size_t)t1 * (N_FEATURES * HIDDEN)) + tf * 16 + tc;
        EpiIn e = {0.f, 0.f, 0.f, 0.f};
        #pragma unroll 16
        for (int i = 0; i < N_FEATURES / 2; ++i) {
            const int f = tf + 2 * i;
            float  xv = xs[warp][1][f];
            float4 wv = w1v[i * 32];
            e.a0 = fmaf(xv, wv.x, e.a0);
            e.a1 = fmaf(xv, wv.y, e.a1);
            e.a2 = fmaf(xv, wv.z, e.a2);
            e.a3 = fmaf(xv, wv.w, e.a3);
        }
        epilogue_store(t1, s1, lane, tc, e, l1_bias, l2_emb, l2_bias, out);
    }
}

extern "C" void kernel_launch(void* const* d_in, const int* in_sizes, int n_in,
                              void* d_out, int out_size) {
    const float* x       = (const float*)d_in[0];
    const int*   taskids = (const int*)  d_in[1];
    const float* l1_emb  = (const float*)d_in[2];
    const float* l1_bias = (const float*)d_in[3];
    const float* l2_emb  = (const float*)d_in[4];
    const float* l2_bias = (const float*)d_in[5];
    float* out = (float*)d_out;

    hypernet_fused<<<CTAS, THREADS>>>(x, taskids, l1_emb, l1_bias,
                                      l2_emb, l2_bias, out);
}

// round 7
// speedup vs baseline: 1.1992x; 1.1992x over previous
#include <cuda_runtime.h>
#include <math.h>

// Problem shapes (fixed by the reference)
#define BATCH      16384
#define N_FEATURES 128
#define HIDDEN     64
#define NUM_TASKS  50000

// Bucketing: task >> 7 -> 391 bins. Duplicates of a task share a bin ->
// adjacent perm slots -> processed concurrently -> L2 dedup of 32KB W1 tiles.
#define BIN_SHIFT 7
#define NBINS     391

// ---------------- prologue: 16 CTAs x 1024 threads, 1 thread per sample ------
#define P_CTAS     16
#define P_THREADS  1024

__device__ int g_hist[NBINS];     // zeroed at load; reset by CTA0 in phase B each run
__device__ int g_cursor[NBINS];   // recomputed each run
__device__ int g_perm[BATCH];     // packed: (task << 14) | sample
__device__ unsigned g_bar_cnt;            // self-resetting arrival counter
__device__ volatile unsigned g_bar_rel[2]; // 2 flags; each barrier clears the other

// 16-CTA grid barrier (all co-resident by construction). Barrier k: last
// arriver clears flag k^1, then sets flag k. Counter self-resets. Flag k is
// always 0 on entry (cleared by the previous barrier / initial state), so the
// state cycle is identical on every graph replay.
__device__ __forceinline__ void pro_barrier(int k) {
    __syncthreads();
    if (threadIdx.x == 0) {
        __threadfence();
        if (atomicAdd(&g_bar_cnt, 1u) == P_CTAS - 1u) {
            atomicExch(&g_bar_cnt, 0u);
            g_bar_rel[k ^ 1] = 0u;
            __threadfence();
            g_bar_rel[k] = 1u;
        }
        while (g_bar_rel[k] == 0u) __nanosleep(64);
        __threadfence();
    }
    __syncthreads();
}

__global__ __launch_bounds__(P_THREADS)
void sort_prologue(const int* __restrict__ task_ids) {
    __shared__ int sbuf[512];

    const int gid = blockIdx.x * P_THREADS + threadIdx.x;   // one sample per thread
    const int t   = task_ids[gid];
    const int bin = t >> BIN_SHIFT;

    // Phase A: global histogram (391 addresses spread over LTS slices)
    atomicAdd(&g_hist[bin], 1);
    pro_barrier(0);

    // Phase B: CTA 0 scans 391 bins -> exclusive prefix in g_cursor, resets hist
    if (blockIdx.x == 0) {
        const int tid = threadIdx.x;
        int c = 0;
        if (tid < 512) {
            c = (tid < NBINS) ? g_hist[tid] : 0;
            sbuf[tid] = c;
        }
        __syncthreads();
        // Hillis-Steele inclusive scan over 512 entries
        #pragma unroll
        for (int off = 1; off < 512; off <<= 1) {
            int v = 0;
            if (tid < 512 && tid >= off) v = sbuf[tid - off];
            __syncthreads();
            if (tid < 512) sbuf[tid] += v;
            __syncthreads();
        }
        if (tid < NBINS) {
            g_cursor[tid] = sbuf[tid] - c;   // exclusive prefix
            g_hist[tid]   = 0;               // reset for next replay
        }
    }
    pro_barrier(1);

    // Phase C: scatter packed (task, sample)
    int pos = atomicAdd(&g_cursor[bin], 1);
    g_perm[pos] = (t << 14) | gid;
}

// ---------------- main kernel: R3-main shape (streaming CTAs) ----------------
#define WARPS_PER_BLOCK 2
#define THREADS (WARPS_PER_BLOCK * 32)

// exact GELU: 0.5*x*(1+erf(x/sqrt(2)))
__device__ __forceinline__ float gelu_exact(float v) {
    return 0.5f * v * (1.0f + erff(v * 0.70710678118654752f));
}

__global__ __launch_bounds__(THREADS)
void hypernet_kernel(const float* __restrict__ x,
                     const float* __restrict__ l1_emb,   // [NUM_TASKS, 128*64]
                     const float* __restrict__ l1_bias,  // [NUM_TASKS, 64]
                     const float* __restrict__ l2_emb,   // [NUM_TASKS, 64]
                     const float* __restrict__ l2_bias,  // [NUM_TASKS, 1]
                     float*       __restrict__ out)      // [BATCH, 1]
{
    __shared__ float xs[WARPS_PER_BLOCK][N_FEATURES];

    const int warp = threadIdx.x >> 5;
    const int lane = threadIdx.x & 31;

    // Sorted slot -> packed (task, sample): one load, no dependent chain.
    const int v      = g_perm[blockIdx.x * WARPS_PER_BLOCK + warp];
    const int sample = v & 0x3FFF;
    const int task   = v >> 14;

    // Stage this sample's x into shared (warp-local, float4, coalesced)
    {
        const float4* xg = reinterpret_cast<const float4*>(x + (size_t)sample * N_FEATURES);
        float4 val = xg[lane];
        reinterpret_cast<float4*>(xs[warp])[lane] = val;
    }
    __syncwarp();

    const float* w1 = l1_emb + (size_t)task * (N_FEATURES * HIDDEN);

    // Lane layout: tf = lane>>4 (2-way split over F), tc = lane&15 (H via float4)
    const int tf = lane >> 4;
    const int tc = lane & 15;

    const float4* w1v = reinterpret_cast<const float4*>(w1) + tf * 16 + tc;

    float a0 = 0.f, a1 = 0.f, a2 = 0.f, a3 = 0.f;

    #pragma unroll 16
    for (int i = 0; i < N_FEATURES / 2; ++i) {
        const int f = tf + 2 * i;
        float  xv = xs[warp][f];
        float4 wv = w1v[i * 32];             // advance 2 rows = 32 float4
        a0 = fmaf(xv, wv.x, a0);
        a1 = fmaf(xv, wv.y, a1);
        a2 = fmaf(xv, wv.z, a2);
        a3 = fmaf(xv, wv.w, a3);
    }

    // Fold the 2-way F split
    a0 += __shfl_xor_sync(0xffffffffu, a0, 16);
    a1 += __shfl_xor_sync(0xffffffffu, a1, 16);
    a2 += __shfl_xor_sync(0xffffffffu, a2, 16);
    a3 += __shfl_xor_sync(0xffffffffu, a3, 16);

    // bias + GELU + dot with w2
    const float4 b1 = reinterpret_cast<const float4*>(l1_bias + (size_t)task * HIDDEN)[tc];
    const float4 w2 = reinterpret_cast<const float4*>(l2_emb  + (size_t)task * HIDDEN)[tc];

    float h0 = gelu_exact(a0 + b1.x);
    float h1 = gelu_exact(a1 + b1.y);
    float h2 = gelu_exact(a2 + b1.z);
    float h3 = gelu_exact(a3 + b1.w);

    float dot = fmaf(h0, w2.x, fmaf(h1, w2.y, fmaf(h2, w2.z, h3 * w2.w)));

    dot += __shfl_xor_sync(0xffffffffu, dot, 8);
    dot += __shfl_xor_sync(0xffffffffu, dot, 4);
    dot += __shfl_xor_sync(0xffffffffu, dot, 2);
    dot += __shfl_xor_sync(0xffffffffu, dot, 1);

    if (lane == 0) {
        out[sample] = dot + __ldg(l2_bias + task);
    }
}

extern "C" void kernel_launch(void* const* d_in, const int* in_sizes, int n_in,
                              void* d_out, int out_size) {
    const float* x       = (const float*)d_in[0];
    const int*   taskids = (const int*)  d_in[1];
    const float* l1_emb  = (const float*)d_in[2];
    const float* l1_bias = (const float*)d_in[3];
    const float* l2_emb  = (const float*)d_in[4];
    const float* l2_bias = (const float*)d_in[5];
    float* out = (float*)d_out;

    sort_prologue<<<P_CTAS, P_THREADS>>>(taskids);

    const int blocks = BATCH / WARPS_PER_BLOCK;   // 8192 blocks of 64 threads
    hypernet_kernel<<<blocks, THREADS>>>(x, l1_emb, l1_bias,
                                         l2_emb, l2_bias, out);
}